// round 10
// baseline (speedup 1.0000x reference)
#include <cuda_runtime.h>
#include <cuda_fp16.h>
#include <math.h>

#define BATCH 64
#define NROW  307
#define NN    614
#define D     64
#define XST   68      // k_wh smem tile stride
#define MAXJ  48      // max row degree bound (observed ~33)
#define NNZCAP 16384  // attention-weight smem capacity (actual nnz ~10.3k)

// ---- device globals (allocation-free scratch) -----------------------------
__device__ __align__(16) __half g_Whh[(size_t)BATCH * NN * D]; // [b][m][c]
__device__ float2 g_l1[(size_t)BATCH * NN];        // [b][n] = {Wh1, exp(Wh1)}
__device__ float2 g_l2[(size_t)BATCH * NN];        // [b][m] = {Wh2, exp(Wh2)}
__device__ int    g_row_idx[NN * NN];
__device__ int    g_row_cnt[NN];
__device__ int    g_col_idx[NN * NN];
__device__ int    g_col_cnt[NN];
__device__ int    g_pos[NN * NN];                  // [m][n] -> p in column m
__device__ int    g_colbase[NN];                   // exclusive scan of col_cnt
__device__ int2   g_cnm[NN * 64];                  // flat col-CSR: {n, m}
__device__ int2   g_jd[NN * MAXJ];                 // [n][j] = {m*128, attw idx}

// ---- helpers --------------------------------------------------------------
__device__ __forceinline__ unsigned cvt_tf32(float f) {
    unsigned r; asm("cvt.rna.tf32.f32 %0, %1;" : "=r"(r) : "f"(f)); return r;
}
__device__ __forceinline__ void mma_tf32(float c[4], unsigned a0, unsigned a1,
                                         unsigned a2, unsigned a3,
                                         unsigned b0, unsigned b1) {
    asm("mma.sync.aligned.m16n8k8.row.col.f32.tf32.tf32.f32 "
        "{%0,%1,%2,%3},{%4,%5,%6,%7},{%8,%9},{%0,%1,%2,%3};"
        : "+f"(c[0]), "+f"(c[1]), "+f"(c[2]), "+f"(c[3])
        : "r"(a0), "r"(a1), "r"(a2), "r"(a3), "r"(b0), "r"(b1));
}
__device__ __forceinline__ void fma8(float acc[8], float w, uint4 raw) {
    float2 f0 = __half22float2(*(const __half2*)&raw.x);
    float2 f1 = __half22float2(*(const __half2*)&raw.y);
    float2 f2 = __half22float2(*(const __half2*)&raw.z);
    float2 f3 = __half22float2(*(const __half2*)&raw.w);
    acc[0] = fmaf(w, f0.x, acc[0]); acc[1] = fmaf(w, f0.y, acc[1]);
    acc[2] = fmaf(w, f1.x, acc[2]); acc[3] = fmaf(w, f1.y, acc[3]);
    acc[4] = fmaf(w, f2.x, acc[4]); acc[5] = fmaf(w, f2.y, acc[5]);
    acc[6] = fmaf(w, f3.x, acc[6]); acc[7] = fmaf(w, f3.y, acc[7]);
}

// ---- fused-kernel smem layout (dynamic) -----------------------------------
#define AL16(x) (((x) + 15) & ~15)
static const int SM_WH   = 0;                                   // 78592 B
static const int SM_ATT  = AL16(SM_WH  + NN * D * 2);           // 65536 B
static const int SM_L1   = AL16(SM_ATT + NNZCAP * 4);           // 4912 B
static const int SM_L2   = AL16(SM_L1  + NN * 8);               // 4912 B
static const int SM_ZI   = AL16(SM_L2  + NN * 8);               // 2456 B
static const int SM_CB   = AL16(SM_ZI  + NN * 4);               // 2456 B
static const int SM_CC   = AL16(SM_CB  + NN * 4);               // 2456 B
static const int SM_RC   = AL16(SM_CC  + NN * 4);               // 2456 B
static const int SM_TOT  = AL16(SM_RC  + NN * 4);

// ---------------------------------------------------------------------------
// Kernel 0: row-CSR + col-CSR + g_pos (proven form).
// ---------------------------------------------------------------------------
__global__ __launch_bounds__(1024) void k_csr(const float* __restrict__ adj) {
    const int tid  = threadIdx.x;
    const int lane = tid & 31;
    const int w    = tid >> 5;
    if (blockIdx.y == 0) {
        const int r = blockIdx.x * 32 + w;
        if (r >= NN) return;
        int cnt = 0;
        for (int m0 = 0; m0 < NN; m0 += 32) {
            int m = m0 + lane;
            float v = (m < NN) ? adj[r * NN + m] : 0.f;
            unsigned msk = __ballot_sync(0xffffffffu, v > 0.f);
            if (v > 0.f)
                g_row_idx[r * NN + cnt + __popc(msk & ((1u << lane) - 1u))] = m;
            cnt += __popc(msk);
        }
        if (lane == 0) g_row_cnt[r] = cnt;
    } else {
        __shared__ float tile[32][33];
        const int cbase = blockIdx.x * 32;
        const int c = cbase + w;
        int cnt = 0;
        for (int n0 = 0; n0 < NN; n0 += 32) {
            int n = n0 + w, m = cbase + lane;
            tile[w][lane] = (n < NN && m < NN) ? adj[n * NN + m] : 0.f;
            __syncthreads();
            if (c < NN) {
                float v = tile[lane][w];
                unsigned msk = __ballot_sync(0xffffffffu, v > 0.f);
                if (v > 0.f) {
                    int p = cnt + __popc(msk & ((1u << lane) - 1u));
                    g_col_idx[c * NN + p] = n0 + lane;
                    g_pos[c * NN + n0 + lane] = p;
                }
                cnt += __popc(msk);
            }
            __syncthreads();
        }
        if (c < NN && lane == 0) g_col_cnt[c] = cnt;
    }
}

// ---------------------------------------------------------------------------
// Kernel 0b: exclusive scan of col counts + flat col-CSR {n,m} list.
// Single block, 1024 threads.
// ---------------------------------------------------------------------------
__global__ __launch_bounds__(1024) void k_scan() {
    __shared__ int s[1024];
    const int tid = threadIdx.x;
    int cnt = (tid < NN) ? g_col_cnt[tid] : 0;
    s[tid] = cnt;
    __syncthreads();
    for (int off = 1; off < 1024; off <<= 1) {
        int v = (tid >= off) ? s[tid - off] : 0;
        __syncthreads();
        s[tid] += v;
        __syncthreads();
    }
    if (tid < NN) {
        int base = s[tid] - cnt;      // exclusive
        g_colbase[tid] = base;
        for (int p = 0; p < cnt; p++)
            g_cnm[base + p] = make_int2(g_col_idx[tid * NN + p], tid);
    }
}

// ---------------------------------------------------------------------------
// Kernel 0c: per-row jump descriptors {Whh byte offset, attw index}.
// ---------------------------------------------------------------------------
__global__ void k_rowpos() {
    const int n   = blockIdx.x;
    const int cnt = g_row_cnt[n];
    for (int j = threadIdx.x; j < cnt; j += 64) {
        int m = g_row_idx[n * NN + j];
        g_jd[n * MAXJ + j] = make_int2(m << 7, g_colbase[m] + g_pos[m * NN + n]);
    }
}

// ---------------------------------------------------------------------------
// Kernel 1: Wh = concat(ht,h)@W via tf32 mma (stored fp16); exact fp32 logits
// + exps stored batch-MAJOR [b][n] (coalesced for the fused kernel).
// ---------------------------------------------------------------------------
__global__ __launch_bounds__(128) void k_wh(const float* __restrict__ h,
                                            const float* __restrict__ ht,
                                            const float* __restrict__ W,
                                            const float* __restrict__ a) {
    const int b     = blockIdx.y;
    const int rbase = blockIdx.x * 64;
    const int tid   = threadIdx.x;

    __shared__ float xs[64 * XST];
    __shared__ float Ws[64 * XST];
    __shared__ float Wa[128];

    for (int k = tid; k < 1024; k += 128) {
        int i = k >> 4, c4 = (k & 15) * 4;
        *(float4*)&Ws[i * XST + c4] = *(const float4*)&W[i * 64 + c4];
    }
    for (int k = tid; k < 1024; k += 128) {
        int r = k >> 4, c4 = (k & 15) * 4;
        int gr = rbase + r;
        float4 v = make_float4(0.f, 0.f, 0.f, 0.f);
        if (gr < NN) {
            const float* src = (gr < NROW) ? &ht[((size_t)b * NROW + gr) * D]
                                           : &h [((size_t)b * NROW + gr - NROW) * D];
            v = *(const float4*)(src + c4);
        }
        *(float4*)&xs[r * XST + c4] = v;
    }
    __syncthreads();

    {   // Wa = W @ a (both halves)
        int kk = tid & 63, which = tid >> 6;
        float s = 0.f;
        for (int c = 0; c < 64; c++)
            s = fmaf(Ws[kk * XST + c], a[which * 64 + c], s);
        Wa[which * 64 + kk] = s;
    }
    __syncthreads();

    const int warp = tid >> 5, lane = tid & 31;
    const int g = lane >> 2, t4 = lane & 3;
    const int m0 = warp * 16;
    float acc[8][4];
#pragma unroll
    for (int nt = 0; nt < 8; nt++)
#pragma unroll
        for (int j = 0; j < 4; j++) acc[nt][j] = 0.f;

#pragma unroll
    for (int ks = 0; ks < 64; ks += 8) {
        unsigned A0 = cvt_tf32(xs[(m0 + g)     * XST + ks + t4]);
        unsigned A1 = cvt_tf32(xs[(m0 + g + 8) * XST + ks + t4]);
        unsigned A2 = cvt_tf32(xs[(m0 + g)     * XST + ks + t4 + 4]);
        unsigned A3 = cvt_tf32(xs[(m0 + g + 8) * XST + ks + t4 + 4]);
#pragma unroll
        for (int nt = 0; nt < 8; nt++) {
            unsigned B0 = cvt_tf32(Ws[(ks + t4)     * XST + nt * 8 + g]);
            unsigned B1 = cvt_tf32(Ws[(ks + t4 + 4) * XST + nt * 8 + g]);
            mma_tf32(acc[nt], A0, A1, A2, A3, B0, B1);
        }
    }

#pragma unroll
    for (int nt = 0; nt < 8; nt++) {
        int col = nt * 8 + t4 * 2;
        int r0 = rbase + m0 + g, r1 = r0 + 8;
        __half2 h0 = __floats2half2_rn(acc[nt][0], acc[nt][1]);
        __half2 h1 = __floats2half2_rn(acc[nt][2], acc[nt][3]);
        if (r0 < NN) *(__half2*)&g_Whh[((size_t)b * NN + r0) * D + col] = h0;
        if (r1 < NN) *(__half2*)&g_Whh[((size_t)b * NN + r1) * D + col] = h1;
    }

    {   // exact fp32 logits + exps, batch-major
        int r = tid & 63, which = tid >> 6;
        float s = 0.f;
#pragma unroll 4
        for (int k2 = 0; k2 < 64; k2++)
            s = fmaf(xs[r * XST + k2], Wa[which * 64 + k2], s);
        int gr = rbase + r;
        if (gr < NN) {
            float2 v = make_float2(s, __expf(s));
            if (which == 0) g_l1[(size_t)b * NN + gr] = v;
            else            g_l2[(size_t)b * NN + gr] = v;
        }
    }
}

// ---------------------------------------------------------------------------
// Kernel 2 (FUSED): one block per batch. Wh[b] + all attention weights live
// in shared memory; aggregation is pure LDS. Replaces k_att + k_out.
// ---------------------------------------------------------------------------
__global__ __launch_bounds__(1024, 1) void k_fused(float* __restrict__ out) {
    extern __shared__ __align__(16) char sm[];
    __half* swh   = (__half*)(sm + SM_WH);
    float*  attw  = (float*) (sm + SM_ATT);
    float2* sl1   = (float2*)(sm + SM_L1);
    float2* sl2   = (float2*)(sm + SM_L2);
    float*  szi   = (float*) (sm + SM_ZI);
    int*    scb   = (int*)   (sm + SM_CB);
    int*    scc   = (int*)   (sm + SM_CC);
    int*    src_  = (int*)   (sm + SM_RC);

    const int b   = blockIdx.x;
    const int tid = threadIdx.x;

    // Phase 1: coalesced loads of this batch's data
    {
        const uint4* g = (const uint4*)(g_Whh + (size_t)b * NN * D);
        uint4* s = (uint4*)swh;
        for (int i = tid; i < NN * D * 2 / 16; i += 1024) s[i] = g[i];
        for (int i = tid; i < NN; i += 1024) {
            sl1[i]  = g_l1[(size_t)b * NN + i];
            sl2[i]  = g_l2[(size_t)b * NN + i];
            scb[i]  = g_colbase[i];
            scc[i]  = g_col_cnt[i];
            src_[i] = g_row_cnt[i];
        }
    }
    __syncthreads();
    const int nnz = scb[NN - 1] + scc[NN - 1];

    // Phase 2a: unnormalized weights over flat col-CSR (separable exp)
    for (int i = tid; i < nnz; i += 1024) {
        int2 cm = g_cnm[i];
        float2 a1 = sl1[cm.x], l2 = sl2[cm.y];
        float s = a1.x + l2.x;
        attw[i] = (s > 0.f) ? a1.y * l2.y : __expf(0.2f * s);
    }
    __syncthreads();

    // Phase 2b: per-column 1/Z
    if (tid < NN) {
        int base = scb[tid], c = scc[tid];
        float z0 = 0.f, z1 = 0.f;
        int p = 0;
        for (; p + 2 <= c; p += 2) { z0 += attw[base + p]; z1 += attw[base + p + 1]; }
        if (p < c) z0 += attw[base + p];
        szi[tid] = 1.f / (z0 + z1);
    }
    __syncthreads();

    // Phase 2c: normalize
    for (int i = tid; i < nnz; i += 1024) {
        int2 cm = g_cnm[i];
        attw[i] *= szi[cm.y];
    }
    __syncthreads();

    // Phase 3: aggregation — pure LDS. slot = rows n, n+128, ...; 8 lanes x 8 ch.
    const int slot = tid >> 3, lane = tid & 7;
    const char* whbase = (const char*)swh + lane * 16;
    for (int n = slot; n < NN; n += 128) {
        const int cnt = src_[n];
        const int2* jd = &g_jd[n * MAXJ];
        float acc[8];
#pragma unroll
        for (int k = 0; k < 8; k++) acc[k] = 0.f;
        int j = 0;
        for (; j + 2 <= cnt; j += 2) {
            int2 d0 = __ldg(&jd[j]), d1 = __ldg(&jd[j + 1]);
            float w0 = attw[d0.y], w1 = attw[d1.y];
            uint4 v0 = *(const uint4*)(whbase + d0.x);
            uint4 v1 = *(const uint4*)(whbase + d1.x);
            fma8(acc, w0, v0);
            fma8(acc, w1, v1);
        }
        if (j < cnt) {
            int2 d0 = __ldg(&jd[j]);
            fma8(acc, attw[d0.y], *(const uint4*)(whbase + d0.x));
        }
#pragma unroll
        for (int k = 0; k < 8; k++)
            acc[k] = (acc[k] > 0.f) ? acc[k] : (__expf(acc[k]) - 1.f);

        size_t ob = (n < NROW) ? (((size_t)b * NROW + n) * 128 + lane * 8)
                               : (((size_t)b * NROW + (n - NROW)) * 128 + 64 + lane * 8);
        *(float4*)(out + ob)     = make_float4(acc[0], acc[1], acc[2], acc[3]);
        *(float4*)(out + ob + 4) = make_float4(acc[4], acc[5], acc[6], acc[7]);
    }
}

// ---------------------------------------------------------------------------
extern "C" void kernel_launch(void* const* d_in, const int* in_sizes, int n_in,
                              void* d_out, int out_size) {
    const float* h   = (const float*)d_in[0];
    const float* ht  = (const float*)d_in[1];
    const float* W   = (const float*)d_in[2];
    const float* a   = (const float*)d_in[3];
    const float* adj = (const float*)d_in[4];
    float* out = (float*)d_out;

    cudaFuncSetAttribute(k_fused, cudaFuncAttributeMaxDynamicSharedMemorySize, SM_TOT);

    k_csr<<<dim3((NN + 31) / 32, 2), 1024>>>(adj);
    k_wh<<<dim3((NN + 63) / 64, BATCH), 128>>>(h, ht, W, a);
    k_scan<<<1, 1024>>>();
    k_rowpos<<<NN, 64>>>();
    k_fused<<<BATCH, 1024, SM_TOT>>>(out);
}

// round 11
// speedup vs baseline: 1.3361x; 1.3361x over previous
#include <cuda_runtime.h>
#include <cuda_fp16.h>
#include <math.h>

#define BATCH 64
#define NROW  307
#define NN    614
#define D     64
#define XST   68     // k_wh smem tile stride
#define MAXJ  64     // degree bound (observed ~33; binomial tail < 40)

// ---- device globals (allocation-free scratch) -----------------------------
__device__ __align__(16) __half g_Whh[(size_t)BATCH * NN * D]; // [b][m][c]
__device__ float2 g_l1[(size_t)BATCH * NN];    // [b][n] = {Wh1, exp(Wh1)}
__device__ float2 g_l2[(size_t)BATCH * NN];    // [b][m] = {Wh2, exp(Wh2)}
__device__ float  g_zinv[(size_t)BATCH * NN];  // [b][m] = 1/Z column m
__device__ int    g_jd [NN * MAXJ];            // [n][j] = m   (row CSR, dense)
__device__ int    g_cid[NN * MAXJ];            // [m][p] = n   (col CSR, dense)
__device__ int    g_row_cnt[NN];
__device__ int    g_col_cnt[NN];

// ---- helpers --------------------------------------------------------------
__device__ __forceinline__ unsigned cvt_tf32(float f) {
    unsigned r; asm("cvt.rna.tf32.f32 %0, %1;" : "=r"(r) : "f"(f)); return r;
}
__device__ __forceinline__ void mma_tf32(float c[4], unsigned a0, unsigned a1,
                                         unsigned a2, unsigned a3,
                                         unsigned b0, unsigned b1) {
    asm("mma.sync.aligned.m16n8k8.row.col.f32.tf32.tf32.f32 "
        "{%0,%1,%2,%3},{%4,%5,%6,%7},{%8,%9},{%0,%1,%2,%3};"
        : "+f"(c[0]), "+f"(c[1]), "+f"(c[2]), "+f"(c[3])
        : "r"(a0), "r"(a1), "r"(a2), "r"(a3), "r"(b0), "r"(b1));
}
__device__ __forceinline__ void fma8(float acc[8], float w, uint4 raw) {
    float2 f0 = __half22float2(*(const __half2*)&raw.x);
    float2 f1 = __half22float2(*(const __half2*)&raw.y);
    float2 f2 = __half22float2(*(const __half2*)&raw.z);
    float2 f3 = __half22float2(*(const __half2*)&raw.w);
    acc[0] = fmaf(w, f0.x, acc[0]); acc[1] = fmaf(w, f0.y, acc[1]);
    acc[2] = fmaf(w, f1.x, acc[2]); acc[3] = fmaf(w, f1.y, acc[3]);
    acc[4] = fmaf(w, f2.x, acc[4]); acc[5] = fmaf(w, f2.y, acc[5]);
    acc[6] = fmaf(w, f3.x, acc[6]); acc[7] = fmaf(w, f3.y, acc[7]);
}

// ---------------------------------------------------------------------------
// Kernel 0: dense row/col CSR of (adj>0). Row pass coalesced; col pass via
// 32x33 smem-tile transpose.
// ---------------------------------------------------------------------------
__global__ __launch_bounds__(1024) void k_csr(const float* __restrict__ adj) {
    const int tid  = threadIdx.x;
    const int lane = tid & 31;
    const int w    = tid >> 5;
    if (blockIdx.y == 0) {
        const int r = blockIdx.x * 32 + w;
        if (r >= NN) return;
        int cnt = 0;
        for (int m0 = 0; m0 < NN; m0 += 32) {
            int m = m0 + lane;
            float v = (m < NN) ? adj[r * NN + m] : 0.f;
            unsigned msk = __ballot_sync(0xffffffffu, v > 0.f);
            if (v > 0.f) {
                int pos = cnt + __popc(msk & ((1u << lane) - 1u));
                if (pos < MAXJ) g_jd[r * MAXJ + pos] = m;
            }
            cnt += __popc(msk);
        }
        if (lane == 0) g_row_cnt[r] = min(cnt, MAXJ);
    } else {
        __shared__ float tile[32][33];
        const int cbase = blockIdx.x * 32;
        const int c = cbase + w;
        int cnt = 0;
        for (int n0 = 0; n0 < NN; n0 += 32) {
            int n = n0 + w, m = cbase + lane;
            tile[w][lane] = (n < NN && m < NN) ? adj[n * NN + m] : 0.f;
            __syncthreads();
            if (c < NN) {
                float v = tile[lane][w];
                unsigned msk = __ballot_sync(0xffffffffu, v > 0.f);
                if (v > 0.f) {
                    int p = cnt + __popc(msk & ((1u << lane) - 1u));
                    if (p < MAXJ) g_cid[c * MAXJ + p] = n0 + lane;
                }
                cnt += __popc(msk);
            }
            __syncthreads();
        }
        if (c < NN && lane == 0) g_col_cnt[c] = min(cnt, MAXJ);
    }
}

// ---------------------------------------------------------------------------
// Kernel 1: Wh = concat(ht,h)@W via tf32 mma (stored fp16); exact fp32 logits
// + exps stored batch-major [b][n].
// ---------------------------------------------------------------------------
__global__ __launch_bounds__(128) void k_wh(const float* __restrict__ h,
                                            const float* __restrict__ ht,
                                            const float* __restrict__ W,
                                            const float* __restrict__ a) {
    const int b     = blockIdx.y;
    const int rbase = blockIdx.x * 64;
    const int tid   = threadIdx.x;

    __shared__ float xs[64 * XST];
    __shared__ float Ws[64 * XST];
    __shared__ float Wa[128];

    for (int k = tid; k < 1024; k += 128) {
        int i = k >> 4, c4 = (k & 15) * 4;
        *(float4*)&Ws[i * XST + c4] = *(const float4*)&W[i * 64 + c4];
    }
    for (int k = tid; k < 1024; k += 128) {
        int r = k >> 4, c4 = (k & 15) * 4;
        int gr = rbase + r;
        float4 v = make_float4(0.f, 0.f, 0.f, 0.f);
        if (gr < NN) {
            const float* src = (gr < NROW) ? &ht[((size_t)b * NROW + gr) * D]
                                           : &h [((size_t)b * NROW + gr - NROW) * D];
            v = *(const float4*)(src + c4);
        }
        *(float4*)&xs[r * XST + c4] = v;
    }
    __syncthreads();

    {   // Wa = W @ a (both halves)
        int kk = tid & 63, which = tid >> 6;
        float s = 0.f;
        for (int c = 0; c < 64; c++)
            s = fmaf(Ws[kk * XST + c], a[which * 64 + c], s);
        Wa[which * 64 + kk] = s;
    }
    __syncthreads();

    const int warp = tid >> 5, lane = tid & 31;
    const int g = lane >> 2, t4 = lane & 3;
    const int m0 = warp * 16;
    float acc[8][4];
#pragma unroll
    for (int nt = 0; nt < 8; nt++)
#pragma unroll
        for (int j = 0; j < 4; j++) acc[nt][j] = 0.f;

#pragma unroll
    for (int ks = 0; ks < 64; ks += 8) {
        unsigned A0 = cvt_tf32(xs[(m0 + g)     * XST + ks + t4]);
        unsigned A1 = cvt_tf32(xs[(m0 + g + 8) * XST + ks + t4]);
        unsigned A2 = cvt_tf32(xs[(m0 + g)     * XST + ks + t4 + 4]);
        unsigned A3 = cvt_tf32(xs[(m0 + g + 8) * XST + ks + t4 + 4]);
#pragma unroll
        for (int nt = 0; nt < 8; nt++) {
            unsigned B0 = cvt_tf32(Ws[(ks + t4)     * XST + nt * 8 + g]);
            unsigned B1 = cvt_tf32(Ws[(ks + t4 + 4) * XST + nt * 8 + g]);
            mma_tf32(acc[nt], A0, A1, A2, A3, B0, B1);
        }
    }

#pragma unroll
    for (int nt = 0; nt < 8; nt++) {
        int col = nt * 8 + t4 * 2;
        int r0 = rbase + m0 + g, r1 = r0 + 8;
        __half2 h0 = __floats2half2_rn(acc[nt][0], acc[nt][1]);
        __half2 h1 = __floats2half2_rn(acc[nt][2], acc[nt][3]);
        if (r0 < NN) *(__half2*)&g_Whh[((size_t)b * NN + r0) * D + col] = h0;
        if (r1 < NN) *(__half2*)&g_Whh[((size_t)b * NN + r1) * D + col] = h1;
    }

    {   // exact fp32 logits + exps, batch-major
        int r = tid & 63, which = tid >> 6;
        float s = 0.f;
#pragma unroll 4
        for (int k2 = 0; k2 < 64; k2++)
            s = fmaf(xs[r * XST + k2], Wa[which * 64 + k2], s);
        int gr = rbase + r;
        if (gr < NN) {
            float2 v = make_float2(s, __expf(s));
            if (which == 0) g_l1[(size_t)b * NN + gr] = v;
            else            g_l2[(size_t)b * NN + gr] = v;
        }
    }
}

// ---------------------------------------------------------------------------
// Kernel 2: per-(m,b) column softmax denominators (max-free, separable exp).
// Grid (m-chunks, b): block works a fixed b -> l1[b][*] region is L1-hot.
// ---------------------------------------------------------------------------
__global__ __launch_bounds__(128) void k_colstats() {
    const int tid  = threadIdx.x;
    const int unit = tid >> 3, lane = tid & 7;
    const int m    = blockIdx.x * 16 + unit;
    const int b    = blockIdx.y;
    if (m >= NN) return;
    const int cnt = g_col_cnt[m];
    const float2 l2 = g_l2[(size_t)b * NN + m];
    const float2* __restrict__ l1p = &g_l1[(size_t)b * NN];
    float Z = 0.f;
    for (int k = lane; k < cnt; k += 8) {
        int n = g_cid[m * MAXJ + k];
        float2 l1 = __ldg(&l1p[n]);
        float s = l1.x + l2.x;
        Z += (s > 0.f) ? l1.y * l2.y : __expf(0.2f * s);
    }
#pragma unroll
    for (int off = 4; off > 0; off >>= 1)
        Z += __shfl_xor_sync(0xffffffffu, Z, off, 8);
    if (lane == 0) g_zinv[(size_t)b * NN + m] = 1.f / Z;
}

// ---------------------------------------------------------------------------
// Kernel 3: batch-resident aggregation. Block = (n-chunk of 128, batch b);
// all gathers (Whh[b] 78KB, l2/zinv ~7KB) target one L1-resident region.
// 512 threads = 64 slots x 8 lanes; each slot handles 2 rows.
// ---------------------------------------------------------------------------
__global__ __launch_bounds__(512) void k_agg(float* __restrict__ out) {
    const int b    = blockIdx.y;
    const int base = blockIdx.x * 128;
    const int tid  = threadIdx.x;
    const int slot = tid >> 3, lane = tid & 7;

    __shared__ float2 sl1[128];
    if (tid < 128 && base + tid < NN)
        sl1[tid] = g_l1[(size_t)b * NN + base + tid];
    __syncthreads();

    const char*   whb = (const char*)g_Whh + (size_t)b * NN * 128 + lane * 16;
    const float2* l2p = &g_l2[(size_t)b * NN];
    const float*  zip = &g_zinv[(size_t)b * NN];

#pragma unroll
    for (int half = 0; half < 2; half++) {
        const int n = base + slot + half * 64;
        if (n < NN) {
            const float2 l1v = sl1[slot + half * 64];
            const int cnt = g_row_cnt[n];
            const int* __restrict__ ji = &g_jd[n * MAXJ];

            float acc[8];
#pragma unroll
            for (int k = 0; k < 8; k++) acc[k] = 0.f;

            int j = 0;
            for (; j + 2 <= cnt; j += 2) {
                int m0 = __ldg(&ji[j]), m1 = __ldg(&ji[j + 1]);
                float2 l20 = __ldg(&l2p[m0]);
                float2 l21 = __ldg(&l2p[m1]);
                float  zi0 = __ldg(&zip[m0]);
                float  zi1 = __ldg(&zip[m1]);
                uint4  v0  = __ldg((const uint4*)(whb + (m0 << 7)));
                uint4  v1  = __ldg((const uint4*)(whb + (m1 << 7)));
                float s0 = l1v.x + l20.x;
                float s1 = l1v.x + l21.x;
                float w0 = ((s0 > 0.f) ? l1v.y * l20.y : __expf(0.2f * s0)) * zi0;
                float w1 = ((s1 > 0.f) ? l1v.y * l21.y : __expf(0.2f * s1)) * zi1;
                fma8(acc, w0, v0);
                fma8(acc, w1, v1);
            }
            if (j < cnt) {
                int m0 = __ldg(&ji[j]);
                float2 l20 = __ldg(&l2p[m0]);
                float  zi0 = __ldg(&zip[m0]);
                uint4  v0  = __ldg((const uint4*)(whb + (m0 << 7)));
                float s0 = l1v.x + l20.x;
                float w0 = ((s0 > 0.f) ? l1v.y * l20.y : __expf(0.2f * s0)) * zi0;
                fma8(acc, w0, v0);
            }

#pragma unroll
            for (int k = 0; k < 8; k++)
                acc[k] = (acc[k] > 0.f) ? acc[k] : (__expf(acc[k]) - 1.f);

            size_t ob = (n < NROW)
                ? (((size_t)b * NROW + n) * 128 + lane * 8)
                : (((size_t)b * NROW + (n - NROW)) * 128 + 64 + lane * 8);
            *(float4*)(out + ob)     = make_float4(acc[0], acc[1], acc[2], acc[3]);
            *(float4*)(out + ob + 4) = make_float4(acc[4], acc[5], acc[6], acc[7]);
        }
    }
}

// ---------------------------------------------------------------------------
extern "C" void kernel_launch(void* const* d_in, const int* in_sizes, int n_in,
                              void* d_out, int out_size) {
    const float* h   = (const float*)d_in[0];
    const float* ht  = (const float*)d_in[1];
    const float* W   = (const float*)d_in[2];
    const float* a   = (const float*)d_in[3];
    const float* adj = (const float*)d_in[4];
    float* out = (float*)d_out;

    k_csr<<<dim3((NN + 31) / 32, 2), 1024>>>(adj);
    k_wh<<<dim3((NN + 63) / 64, BATCH), 128>>>(h, ht, W, a);
    k_colstats<<<dim3((NN + 15) / 16, BATCH), 128>>>();
    k_agg<<<dim3((NN + 127) / 128, BATCH), 512>>>(out);
}

// round 12
// speedup vs baseline: 1.6359x; 1.2243x over previous
#include <cuda_runtime.h>
#include <cuda_fp16.h>
#include <math.h>

#define BATCH 64
#define NROW  307
#define NN    614
#define D     64
#define XST   68   // smem tile stride (conflict-free for mma frag loads)
#define MAXD  128  // max node degree bound (observed ~35; 128 = huge margin)

// Scratch (device globals — allocation-free per harness rules)
__device__ __align__(16) __half g_Whh[(size_t)BATCH * NN * D];   // [b][m][c] fp16
__device__ float2  g_l1[NN * BATCH];               // [n][b] = {Wh1, exp(Wh1)}
__device__ float2  g_l2[NN * BATCH];               // [m][b] = {Wh2, exp(Wh2)}
__device__ float   g_att[(size_t)NN * MAXD * BATCH]; // [m][p][b] normalized att
__device__ int     g_row_idx[NN * NN];
__device__ int     g_row_cnt[NN];
__device__ int     g_col_idx[NN * NN];
__device__ int     g_col_cnt[NN];
__device__ int     g_pos[NN * NN];                 // [m][n] -> p (col position)

__device__ __forceinline__ unsigned cvt_tf32(float f) {
    unsigned r; asm("cvt.rna.tf32.f32 %0, %1;" : "=r"(r) : "f"(f)); return r;
}
__device__ __forceinline__ void mma_tf32(float c[4], unsigned a0, unsigned a1,
                                         unsigned a2, unsigned a3,
                                         unsigned b0, unsigned b1) {
    asm("mma.sync.aligned.m16n8k8.row.col.f32.tf32.tf32.f32 "
        "{%0,%1,%2,%3},{%4,%5,%6,%7},{%8,%9},{%0,%1,%2,%3};"
        : "+f"(c[0]), "+f"(c[1]), "+f"(c[2]), "+f"(c[3])
        : "r"(a0), "r"(a1), "r"(a2), "r"(a3), "r"(b0), "r"(b1));
}
__device__ __forceinline__ void fma8(float acc[8], float w, uint4 raw) {
    float2 f0 = __half22float2(*(const __half2*)&raw.x);
    float2 f1 = __half22float2(*(const __half2*)&raw.y);
    float2 f2 = __half22float2(*(const __half2*)&raw.z);
    float2 f3 = __half22float2(*(const __half2*)&raw.w);
    acc[0] = fmaf(w, f0.x, acc[0]); acc[1] = fmaf(w, f0.y, acc[1]);
    acc[2] = fmaf(w, f1.x, acc[2]); acc[3] = fmaf(w, f1.y, acc[3]);
    acc[4] = fmaf(w, f2.x, acc[4]); acc[5] = fmaf(w, f2.y, acc[5]);
    acc[6] = fmaf(w, f3.x, acc[6]); acc[7] = fmaf(w, f3.y, acc[7]);
}

// ---------------------------------------------------------------------------
// Kernel 0: row-CSR + col-CSR of (adj>0); col pass also scatters g_pos[m][n].
// ---------------------------------------------------------------------------
__global__ __launch_bounds__(1024) void k_csr(const float* __restrict__ adj) {
    const int tid  = threadIdx.x;
    const int lane = tid & 31;
    const int w    = tid >> 5;               // warp 0..31
    if (blockIdx.y == 0) {
        const int r = blockIdx.x * 32 + w;
        if (r >= NN) return;
        int cnt = 0;
        for (int m0 = 0; m0 < NN; m0 += 32) {
            int m = m0 + lane;
            float v = (m < NN) ? adj[r * NN + m] : 0.f;
            unsigned msk = __ballot_sync(0xffffffffu, v > 0.f);
            if (v > 0.f)
                g_row_idx[r * NN + cnt + __popc(msk & ((1u << lane) - 1u))] = m;
            cnt += __popc(msk);
        }
        if (lane == 0) g_row_cnt[r] = cnt;
    } else {
        __shared__ float tile[32][33];
        const int cbase = blockIdx.x * 32;
        const int c = cbase + w;              // this warp's column
        int cnt = 0;
        for (int n0 = 0; n0 < NN; n0 += 32) {
            int n = n0 + w, m = cbase + lane;
            tile[w][lane] = (n < NN && m < NN) ? adj[n * NN + m] : 0.f;
            __syncthreads();
            if (c < NN) {
                float v = tile[lane][w];
                unsigned msk = __ballot_sync(0xffffffffu, v > 0.f);
                if (v > 0.f) {
                    int p = cnt + __popc(msk & ((1u << lane) - 1u));
                    g_col_idx[c * NN + p] = n0 + lane;
                    g_pos[c * NN + n0 + lane] = p;
                }
                cnt += __popc(msk);
            }
            __syncthreads();
        }
        if (c < NN && lane == 0) g_col_cnt[c] = cnt;
    }
}

// ---------------------------------------------------------------------------
// Kernel 1: Wh = concat(ht,h)@W via tf32 mma (stored fp16); exact fp32 logits
// stored batch-minor as {val, exp(val)} pairs for separable softmax weights.
// ---------------------------------------------------------------------------
__global__ __launch_bounds__(128) void k_wh(const float* __restrict__ h,
                                            const float* __restrict__ ht,
                                            const float* __restrict__ W,
                                            const float* __restrict__ a) {
    const int b     = blockIdx.y;
    const int rbase = blockIdx.x * 64;
    const int tid   = threadIdx.x;

    __shared__ float xs[64 * XST];
    __shared__ float Ws[64 * XST];
    __shared__ float Wa[128];

    for (int k = tid; k < 1024; k += 128) {
        int i = k >> 4, c4 = (k & 15) * 4;
        *(float4*)&Ws[i * XST + c4] = *(const float4*)&W[i * 64 + c4];
    }
    for (int k = tid; k < 1024; k += 128) {
        int r = k >> 4, c4 = (k & 15) * 4;
        int gr = rbase + r;
        float4 v = make_float4(0.f, 0.f, 0.f, 0.f);
        if (gr < NN) {
            const float* src = (gr < NROW) ? &ht[((size_t)b * NROW + gr) * D]
                                           : &h [((size_t)b * NROW + gr - NROW) * D];
            v = *(const float4*)(src + c4);
        }
        *(float4*)&xs[r * XST + c4] = v;
    }
    __syncthreads();

    {   // Wa[0:64] = W@a[:64], Wa[64:128] = W@a[64:]
        int kk = tid & 63, which = tid >> 6;
        float s = 0.f;
        for (int c = 0; c < 64; c++)
            s = fmaf(Ws[kk * XST + c], a[which * 64 + c], s);
        Wa[which * 64 + kk] = s;
    }
    __syncthreads();

    const int warp = tid >> 5, lane = tid & 31;
    const int g = lane >> 2, t4 = lane & 3;
    const int m0 = warp * 16;
    float acc[8][4];
#pragma unroll
    for (int nt = 0; nt < 8; nt++)
#pragma unroll
        for (int j = 0; j < 4; j++) acc[nt][j] = 0.f;

#pragma unroll
    for (int ks = 0; ks < 64; ks += 8) {
        unsigned A0 = cvt_tf32(xs[(m0 + g)     * XST + ks + t4]);
        unsigned A1 = cvt_tf32(xs[(m0 + g + 8) * XST + ks + t4]);
        unsigned A2 = cvt_tf32(xs[(m0 + g)     * XST + ks + t4 + 4]);
        unsigned A3 = cvt_tf32(xs[(m0 + g + 8) * XST + ks + t4 + 4]);
#pragma unroll
        for (int nt = 0; nt < 8; nt++) {
            unsigned B0 = cvt_tf32(Ws[(ks + t4)     * XST + nt * 8 + g]);
            unsigned B1 = cvt_tf32(Ws[(ks + t4 + 4) * XST + nt * 8 + g]);
            mma_tf32(acc[nt], A0, A1, A2, A3, B0, B1);
        }
    }

#pragma unroll
    for (int nt = 0; nt < 8; nt++) {
        int col = nt * 8 + t4 * 2;
        int r0 = rbase + m0 + g, r1 = r0 + 8;
        __half2 h0 = __floats2half2_rn(acc[nt][0], acc[nt][1]);
        __half2 h1 = __floats2half2_rn(acc[nt][2], acc[nt][3]);
        if (r0 < NN) *(__half2*)&g_Whh[((size_t)b * NN + r0) * D + col] = h0;
        if (r1 < NN) *(__half2*)&g_Whh[((size_t)b * NN + r1) * D + col] = h1;
    }

    {   // Exact fp32 logits + their exps (separable softmax numerators)
        int r = tid & 63, which = tid >> 6;
        float s = 0.f;
#pragma unroll 4
        for (int k2 = 0; k2 < 64; k2++)
            s = fmaf(xs[r * XST + k2], Wa[which * 64 + k2], s);
        int gr = rbase + r;
        if (gr < NN) {
            float2 v = make_float2(s, __expf(s));
            if (which == 0) g_l1[gr * BATCH + b] = v;
            else            g_l2[gr * BATCH + b] = v;
        }
    }
}

// ---------------------------------------------------------------------------
// Kernel 2: normalized attention table — barrier-free, ILP-2.
// 128 threads = 2 columns per block (thread = (column-half, batch b)).
// ---------------------------------------------------------------------------
__global__ __launch_bounds__(128) void k_att() {
    const int m = blockIdx.x * 2 + (threadIdx.x >> 6);
    if (m >= NN) return;
    const int b = threadIdx.x & 63;          // 0..63
    const int cnt = g_col_cnt[m];
    const float2 l2 = g_l2[m * BATCH + b];
    const int* __restrict__ ci = &g_col_idx[m * NN];
    float* dst = &g_att[(size_t)m * MAXD * BATCH + b];

    float Z0 = 0.f, Z1 = 0.f;
    int p = 0;
    for (; p + 2 <= cnt; p += 2) {
        int n0 = __ldg(&ci[p]), n1 = __ldg(&ci[p + 1]);
        float2 a0 = g_l1[n0 * BATCH + b];
        float2 a1 = g_l1[n1 * BATCH + b];
        float s0 = a0.x + l2.x, s1 = a1.x + l2.x;
        float e0 = (s0 > 0.f) ? a0.y * l2.y : __expf(0.2f * s0);
        float e1 = (s1 > 0.f) ? a1.y * l2.y : __expf(0.2f * s1);
        dst[p * BATCH]       = e0;
        dst[(p + 1) * BATCH] = e1;
        Z0 += e0; Z1 += e1;
    }
    if (p < cnt) {
        float2 a0 = g_l1[__ldg(&ci[p]) * BATCH + b];
        float s0 = a0.x + l2.x;
        float e0 = (s0 > 0.f) ? a0.y * l2.y : __expf(0.2f * s0);
        dst[p * BATCH] = e0;
        Z0 += e0;
    }
    const float zi = 1.f / (Z0 + Z1);
    for (int q = 0; q < cnt; q++)
        dst[q * BATCH] *= zi;
}

// ---------------------------------------------------------------------------
// Kernel 3: h_prime[b,n,:] = sum_j att * Wh[b,m_j,:]; concat + ELU.
// Grid (614, 2) x 256 threads: block = (n, batch-half of 32), 8 lanes/b.
// Software-pipelined gather (R9-proven).
// ---------------------------------------------------------------------------
__global__ __launch_bounds__(256) void k_out(float* __restrict__ out) {
    const int n    = blockIdx.x;
    const int tid  = threadIdx.x;
    const int b    = (blockIdx.y << 5) + (tid >> 3);   // 0..63
    const int lane = tid & 7;
    const int cnt  = g_row_cnt[n];

    __shared__ int2 sjd[MAXD];        // {wh byte-off, att index base}
    if (tid < cnt) {
        int m = g_row_idx[n * NN + tid];
        int p = g_pos[m * NN + n];
        sjd[tid] = make_int2(m << 7, (m * MAXD + p) * BATCH);
    }
    __syncthreads();

    const char* whb = (const char*)g_Whh + (size_t)b * NN * 128 + lane * 16;

    float acc[8];
#pragma unroll
    for (int k = 0; k < 8; k++) acc[k] = 0.f;

    float w[4]; uint4 r[4];
    const int nb = cnt >> 2;          // full batches of 4

    if (nb > 0) {
#pragma unroll
        for (int u = 0; u < 4; u++) {
            int2 d = sjd[u];
            w[u] = g_att[d.y + b];
            r[u] = *(const uint4*)(whb + d.x);
        }
        for (int kb = 1; kb < nb; kb++) {
            float wn[4]; uint4 rn[4];
#pragma unroll
            for (int u = 0; u < 4; u++) {
                int2 d = sjd[kb * 4 + u];
                wn[u] = g_att[d.y + b];
                rn[u] = *(const uint4*)(whb + d.x);
            }
#pragma unroll
            for (int u = 0; u < 4; u++) fma8(acc, w[u], r[u]);
#pragma unroll
            for (int u = 0; u < 4; u++) { w[u] = wn[u]; r[u] = rn[u]; }
        }
#pragma unroll
        for (int u = 0; u < 4; u++) fma8(acc, w[u], r[u]);
    }
    for (int j = nb << 2; j < cnt; j++) {
        int2 d = sjd[j];
        float wj = g_att[d.y + b];
        uint4 rj = *(const uint4*)(whb + d.x);
        fma8(acc, wj, rj);
    }

#pragma unroll
    for (int k = 0; k < 8; k++)
        acc[k] = (acc[k] > 0.f) ? acc[k] : (__expf(acc[k]) - 1.f);

    size_t ob = (n < NROW) ? (((size_t)b * NROW + n) * 128 + lane * 8)
                           : (((size_t)b * NROW + (n - NROW)) * 128 + 64 + lane * 8);
    *(float4*)(out + ob)     = make_float4(acc[0], acc[1], acc[2], acc[3]);
    *(float4*)(out + ob + 4) = make_float4(acc[4], acc[5], acc[6], acc[7]);
}

// ---------------------------------------------------------------------------
// Launcher with capture-safe fork/join: k_csr (adj-only) runs on a side
// stream concurrently with k_wh (inputs-only); both join before k_att.
// Streams/events created once (host resources only — no device allocation).
// ---------------------------------------------------------------------------
extern "C" void kernel_launch(void* const* d_in, const int* in_sizes, int n_in,
                              void* d_out, int out_size) {
    const float* h   = (const float*)d_in[0];
    const float* ht  = (const float*)d_in[1];
    const float* W   = (const float*)d_in[2];
    const float* a   = (const float*)d_in[3];
    const float* adj = (const float*)d_in[4];
    float* out = (float*)d_out;

    static cudaStream_t s_side = nullptr;
    static cudaEvent_t  e_fork = nullptr, e_join = nullptr;
    if (s_side == nullptr) {
        cudaStreamCreateWithFlags(&s_side, cudaStreamNonBlocking);
        cudaEventCreateWithFlags(&e_fork, cudaEventDisableTiming);
        cudaEventCreateWithFlags(&e_join, cudaEventDisableTiming);
    }

    // fork: side stream inherits capture dependency from the main stream
    cudaEventRecord(e_fork, 0);
    cudaStreamWaitEvent(s_side, e_fork, 0);

    k_csr<<<dim3((NN + 31) / 32, 2), 1024, 0, s_side>>>(adj);
    k_wh<<<dim3((NN + 63) / 64, BATCH), 128>>>(h, ht, W, a);

    // join: main stream waits for k_csr
    cudaEventRecord(e_join, s_side);
    cudaStreamWaitEvent(0, e_join, 0);

    k_att<<<(NN + 1) / 2, 128>>>();
    k_out<<<dim3(NN, 2), 256>>>(out);
}

// round 13
// speedup vs baseline: 1.7777x; 1.0867x over previous
#include <cuda_runtime.h>
#include <cuda_fp16.h>
#include <math.h>

#define BATCH 64
#define HALF  32
#define NROW  307
#define NN    614
#define D     64
#define XST   68   // smem tile stride (conflict-free for mma frag loads)
#define MAXD  128  // max node degree bound (observed ~35)

// Scratch (device globals — allocation-free per harness rules)
__device__ __align__(16) __half g_Whh[(size_t)BATCH * NN * D];   // [b][m][c] fp16
__device__ float2  g_l1[NN * BATCH];               // [n][b] = {Wh1, exp(Wh1)}
__device__ float2  g_l2[NN * BATCH];               // [m][b] = {Wh2, exp(Wh2)}
__device__ float   g_att[(size_t)NN * MAXD * BATCH]; // [m][p][b] normalized att
__device__ int     g_row_idx[NN * NN];
__device__ int     g_row_cnt[NN];
__device__ int     g_col_idx[NN * NN];
__device__ int     g_col_cnt[NN];
__device__ int     g_pos[NN * NN];                 // [m][n] -> p (col position)

__device__ __forceinline__ unsigned cvt_tf32(float f) {
    unsigned r; asm("cvt.rna.tf32.f32 %0, %1;" : "=r"(r) : "f"(f)); return r;
}
__device__ __forceinline__ void mma_tf32(float c[4], unsigned a0, unsigned a1,
                                         unsigned a2, unsigned a3,
                                         unsigned b0, unsigned b1) {
    asm("mma.sync.aligned.m16n8k8.row.col.f32.tf32.tf32.f32 "
        "{%0,%1,%2,%3},{%4,%5,%6,%7},{%8,%9},{%0,%1,%2,%3};"
        : "+f"(c[0]), "+f"(c[1]), "+f"(c[2]), "+f"(c[3])
        : "r"(a0), "r"(a1), "r"(a2), "r"(a3), "r"(b0), "r"(b1));
}
__device__ __forceinline__ void fma8(float acc[8], float w, uint4 raw) {
    float2 f0 = __half22float2(*(const __half2*)&raw.x);
    float2 f1 = __half22float2(*(const __half2*)&raw.y);
    float2 f2 = __half22float2(*(const __half2*)&raw.z);
    float2 f3 = __half22float2(*(const __half2*)&raw.w);
    acc[0] = fmaf(w, f0.x, acc[0]); acc[1] = fmaf(w, f0.y, acc[1]);
    acc[2] = fmaf(w, f1.x, acc[2]); acc[3] = fmaf(w, f1.y, acc[3]);
    acc[4] = fmaf(w, f2.x, acc[4]); acc[5] = fmaf(w, f2.y, acc[5]);
    acc[6] = fmaf(w, f3.x, acc[6]); acc[7] = fmaf(w, f3.y, acc[7]);
}

// ---------------------------------------------------------------------------
// Kernel 0: row-CSR + col-CSR of (adj>0); col pass also scatters g_pos[m][n].
// ---------------------------------------------------------------------------
__global__ __launch_bounds__(1024) void k_csr(const float* __restrict__ adj) {
    const int tid  = threadIdx.x;
    const int lane = tid & 31;
    const int w    = tid >> 5;               // warp 0..31
    if (blockIdx.y == 0) {
        const int r = blockIdx.x * 32 + w;
        if (r >= NN) return;
        int cnt = 0;
        for (int m0 = 0; m0 < NN; m0 += 32) {
            int m = m0 + lane;
            float v = (m < NN) ? adj[r * NN + m] : 0.f;
            unsigned msk = __ballot_sync(0xffffffffu, v > 0.f);
            if (v > 0.f)
                g_row_idx[r * NN + cnt + __popc(msk & ((1u << lane) - 1u))] = m;
            cnt += __popc(msk);
        }
        if (lane == 0) g_row_cnt[r] = cnt;
    } else {
        __shared__ float tile[32][33];
        const int cbase = blockIdx.x * 32;
        const int c = cbase + w;              // this warp's column
        int cnt = 0;
        for (int n0 = 0; n0 < NN; n0 += 32) {
            int n = n0 + w, m = cbase + lane;
            tile[w][lane] = (n < NN && m < NN) ? adj[n * NN + m] : 0.f;
            __syncthreads();
            if (c < NN) {
                float v = tile[lane][w];
                unsigned msk = __ballot_sync(0xffffffffu, v > 0.f);
                if (v > 0.f) {
                    int p = cnt + __popc(msk & ((1u << lane) - 1u));
                    g_col_idx[c * NN + p] = n0 + lane;
                    g_pos[c * NN + n0 + lane] = p;
                }
                cnt += __popc(msk);
            }
            __syncthreads();
        }
        if (c < NN && lane == 0) g_col_cnt[c] = cnt;
    }
}

// ---------------------------------------------------------------------------
// Kernel 1: Wh = concat(ht,h)@W via tf32 mma (stored fp16); exact fp32 logits
// stored batch-minor as {val, exp(val)} pairs. Batch-half via b0 offset.
// ---------------------------------------------------------------------------
__global__ __launch_bounds__(128) void k_wh(const float* __restrict__ h,
                                            const float* __restrict__ ht,
                                            const float* __restrict__ W,
                                            const float* __restrict__ a,
                                            int b0) {
    const int b     = b0 + blockIdx.y;
    const int rbase = blockIdx.x * 64;
    const int tid   = threadIdx.x;

    __shared__ float xs[64 * XST];
    __shared__ float Ws[64 * XST];
    __shared__ float Wa[128];

    for (int k = tid; k < 1024; k += 128) {
        int i = k >> 4, c4 = (k & 15) * 4;
        *(float4*)&Ws[i * XST + c4] = *(const float4*)&W[i * 64 + c4];
    }
    for (int k = tid; k < 1024; k += 128) {
        int r = k >> 4, c4 = (k & 15) * 4;
        int gr = rbase + r;
        float4 v = make_float4(0.f, 0.f, 0.f, 0.f);
        if (gr < NN) {
            const float* src = (gr < NROW) ? &ht[((size_t)b * NROW + gr) * D]
                                           : &h [((size_t)b * NROW + gr - NROW) * D];
            v = *(const float4*)(src + c4);
        }
        *(float4*)&xs[r * XST + c4] = v;
    }
    __syncthreads();

    {   // Wa[0:64] = W@a[:64], Wa[64:128] = W@a[64:]
        int kk = tid & 63, which = tid >> 6;
        float s = 0.f;
        for (int c = 0; c < 64; c++)
            s = fmaf(Ws[kk * XST + c], a[which * 64 + c], s);
        Wa[which * 64 + kk] = s;
    }
    __syncthreads();

    const int warp = tid >> 5, lane = tid & 31;
    const int g = lane >> 2, t4 = lane & 3;
    const int m0 = warp * 16;
    float acc[8][4];
#pragma unroll
    for (int nt = 0; nt < 8; nt++)
#pragma unroll
        for (int j = 0; j < 4; j++) acc[nt][j] = 0.f;

#pragma unroll
    for (int ks = 0; ks < 64; ks += 8) {
        unsigned A0 = cvt_tf32(xs[(m0 + g)     * XST + ks + t4]);
        unsigned A1 = cvt_tf32(xs[(m0 + g + 8) * XST + ks + t4]);
        unsigned A2 = cvt_tf32(xs[(m0 + g)     * XST + ks + t4 + 4]);
        unsigned A3 = cvt_tf32(xs[(m0 + g + 8) * XST + ks + t4 + 4]);
#pragma unroll
        for (int nt = 0; nt < 8; nt++) {
            unsigned B0 = cvt_tf32(Ws[(ks + t4)     * XST + nt * 8 + g]);
            unsigned B1 = cvt_tf32(Ws[(ks + t4 + 4) * XST + nt * 8 + g]);
            mma_tf32(acc[nt], A0, A1, A2, A3, B0, B1);
        }
    }

#pragma unroll
    for (int nt = 0; nt < 8; nt++) {
        int col = nt * 8 + t4 * 2;
        int r0 = rbase + m0 + g, r1 = r0 + 8;
        __half2 h0 = __floats2half2_rn(acc[nt][0], acc[nt][1]);
        __half2 h1 = __floats2half2_rn(acc[nt][2], acc[nt][3]);
        if (r0 < NN) *(__half2*)&g_Whh[((size_t)b * NN + r0) * D + col] = h0;
        if (r1 < NN) *(__half2*)&g_Whh[((size_t)b * NN + r1) * D + col] = h1;
    }

    {   // Exact fp32 logits + their exps (separable softmax numerators)
        int r = tid & 63, which = tid >> 6;
        float s = 0.f;
#pragma unroll 4
        for (int k2 = 0; k2 < 64; k2++)
            s = fmaf(xs[r * XST + k2], Wa[which * 64 + k2], s);
        int gr = rbase + r;
        if (gr < NN) {
            float2 v = make_float2(s, __expf(s));
            if (which == 0) g_l1[gr * BATCH + b] = v;
            else            g_l2[gr * BATCH + b] = v;
        }
    }
}

// ---------------------------------------------------------------------------
// Kernel 2: normalized attention table — barrier-free, ILP-2, batch-half.
// 128 threads = 4 columns x 32 batches (b = b0 + tid&31).
// ---------------------------------------------------------------------------
__global__ __launch_bounds__(128) void k_att(int b0) {
    const int m = blockIdx.x * 4 + (threadIdx.x >> 5);
    if (m >= NN) return;
    const int b = b0 + (threadIdx.x & 31);
    const int cnt = g_col_cnt[m];
    const float2 l2 = g_l2[m * BATCH + b];
    const int* __restrict__ ci = &g_col_idx[m * NN];
    float* dst = &g_att[(size_t)m * MAXD * BATCH + b];

    float Z0 = 0.f, Z1 = 0.f;
    int p = 0;
    for (; p + 2 <= cnt; p += 2) {
        int n0 = __ldg(&ci[p]), n1 = __ldg(&ci[p + 1]);
        float2 a0 = g_l1[n0 * BATCH + b];
        float2 a1 = g_l1[n1 * BATCH + b];
        float s0 = a0.x + l2.x, s1 = a1.x + l2.x;
        float e0 = (s0 > 0.f) ? a0.y * l2.y : __expf(0.2f * s0);
        float e1 = (s1 > 0.f) ? a1.y * l2.y : __expf(0.2f * s1);
        dst[p * BATCH]       = e0;
        dst[(p + 1) * BATCH] = e1;
        Z0 += e0; Z1 += e1;
    }
    if (p < cnt) {
        float2 a0 = g_l1[__ldg(&ci[p]) * BATCH + b];
        float s0 = a0.x + l2.x;
        float e0 = (s0 > 0.f) ? a0.y * l2.y : __expf(0.2f * s0);
        dst[p * BATCH] = e0;
        Z0 += e0;
    }
    const float zi = 1.f / (Z0 + Z1);
    for (int q = 0; q < cnt; q++)
        dst[q * BATCH] *= zi;
}

// ---------------------------------------------------------------------------
// Kernel 3: h_prime[b,n,:] = sum_j att * Wh[b,m_j,:]; concat + ELU.
// Block = (n, batch-half): 256 threads = 32 batches x 8 lanes.
// Depth-2 software pipeline (lower regs -> higher occupancy).
// ---------------------------------------------------------------------------
__global__ __launch_bounds__(256) void k_out(float* __restrict__ out, int b0) {
    const int n    = blockIdx.x;
    const int tid  = threadIdx.x;
    const int b    = b0 + (tid >> 3);   // 32 batches
    const int lane = tid & 7;
    const int cnt  = g_row_cnt[n];

    __shared__ int2 sjd[MAXD];        // {wh byte-off, att index base}
    if (tid < cnt) {
        int m = g_row_idx[n * NN + tid];
        int p = g_pos[m * NN + n];
        sjd[tid] = make_int2(m << 7, (m * MAXD + p) * BATCH);
    }
    __syncthreads();

    const char* whb = (const char*)g_Whh + (size_t)b * NN * 128 + lane * 16;

    float acc[8];
#pragma unroll
    for (int k = 0; k < 8; k++) acc[k] = 0.f;

    float w0, w1; uint4 r0, r1;
    const int nb = cnt >> 1;          // pairs

    if (nb > 0) {
        int2 d0 = sjd[0], d1 = sjd[1];
        w0 = g_att[d0.y + b]; r0 = *(const uint4*)(whb + d0.x);
        w1 = g_att[d1.y + b]; r1 = *(const uint4*)(whb + d1.x);
        for (int kb = 1; kb < nb; kb++) {
            int2 e0 = sjd[kb * 2], e1 = sjd[kb * 2 + 1];
            float nw0 = g_att[e0.y + b]; uint4 nr0 = *(const uint4*)(whb + e0.x);
            float nw1 = g_att[e1.y + b]; uint4 nr1 = *(const uint4*)(whb + e1.x);
            fma8(acc, w0, r0); fma8(acc, w1, r1);
            w0 = nw0; r0 = nr0; w1 = nw1; r1 = nr1;
        }
        fma8(acc, w0, r0); fma8(acc, w1, r1);
    }
    if (cnt & 1) {
        int2 d = sjd[cnt - 1];
        float wj = g_att[d.y + b];
        uint4 rj = *(const uint4*)(whb + d.x);
        fma8(acc, wj, rj);
    }

#pragma unroll
    for (int k = 0; k < 8; k++)
        acc[k] = (acc[k] > 0.f) ? acc[k] : (__expf(acc[k]) - 1.f);

    size_t ob = (n < NROW) ? (((size_t)b * NROW + n) * 128 + lane * 8)
                           : (((size_t)b * NROW + (n - NROW)) * 128 + 64 + lane * 8);
    *(float4*)(out + ob)     = make_float4(acc[0], acc[1], acc[2], acc[3]);
    *(float4*)(out + ob + 4) = make_float4(acc[4], acc[5], acc[6], acc[7]);
}

// ---------------------------------------------------------------------------
// Launcher: two batch-half chains on separate streams + k_csr on a third;
// capture-safe fork/join (host-only resources, created once).
//   s0(main): k_wh(0)  -> [csr] -> k_att(0)  -> k_out(0)
//   s2      : k_wh(32) -> [csr] -> k_att(32) -> k_out(32)
//   s_csr   : k_csr
// ---------------------------------------------------------------------------
extern "C" void kernel_launch(void* const* d_in, const int* in_sizes, int n_in,
                              void* d_out, int out_size) {
    const float* h   = (const float*)d_in[0];
    const float* ht  = (const float*)d_in[1];
    const float* W   = (const float*)d_in[2];
    const float* a   = (const float*)d_in[3];
    const float* adj = (const float*)d_in[4];
    float* out = (float*)d_out;

    static cudaStream_t s_csr = nullptr, s2 = nullptr;
    static cudaEvent_t  eF = nullptr, eC = nullptr, eJ = nullptr;
    if (s_csr == nullptr) {
        cudaStreamCreateWithFlags(&s_csr, cudaStreamNonBlocking);
        cudaStreamCreateWithFlags(&s2,    cudaStreamNonBlocking);
        cudaEventCreateWithFlags(&eF, cudaEventDisableTiming);
        cudaEventCreateWithFlags(&eC, cudaEventDisableTiming);
        cudaEventCreateWithFlags(&eJ, cudaEventDisableTiming);
    }

    // fork
    cudaEventRecord(eF, 0);
    cudaStreamWaitEvent(s_csr, eF, 0);
    cudaStreamWaitEvent(s2,    eF, 0);

    k_csr<<<dim3((NN + 31) / 32, 2), 1024, 0, s_csr>>>(adj);
    cudaEventRecord(eC, s_csr);

    k_wh<<<dim3((NN + 63) / 64, HALF), 128, 0, 0 >>>(h, ht, W, a, 0);
    k_wh<<<dim3((NN + 63) / 64, HALF), 128, 0, s2>>>(h, ht, W, a, HALF);

    cudaStreamWaitEvent(0,  eC, 0);
    cudaStreamWaitEvent(s2, eC, 0);

    k_att<<<(NN + 3) / 4, 128, 0, 0 >>>(0);
    k_att<<<(NN + 3) / 4, 128, 0, s2>>>(HALF);

    k_out<<<NN, 256, 0, 0 >>>(out, 0);
    k_out<<<NN, 256, 0, s2>>>(out, HALF);

    // join
    cudaEventRecord(eJ, s2);
    cudaStreamWaitEvent(0, eJ, 0);
}

// round 14
// speedup vs baseline: 1.7792x; 1.0009x over previous
#include <cuda_runtime.h>
#include <cuda_fp16.h>
#include <math.h>

#define BATCH 64
#define HALF  32
#define NROW  307
#define NN    614
#define D     64
#define XST   68   // smem tile stride (conflict-free for mma frag loads)
#define MAXD  128  // max node degree bound (observed ~35)

// Scratch (device globals — allocation-free per harness rules)
__device__ __align__(16) __half g_Whh[(size_t)BATCH * NN * D];   // [b][m][c] fp16
__device__ float2  g_l1[NN * BATCH];               // [n][b] = {Wh1, exp(Wh1)}
__device__ float2  g_l2[NN * BATCH];               // [m][b] = {Wh2, exp(Wh2)}
__device__ float   g_att[(size_t)NN * MAXD * BATCH]; // [m][p][b] normalized att
__device__ int     g_row_idx[NN * NN];
__device__ int     g_row_cnt[NN];
__device__ int     g_col_idx[NN * NN];
__device__ int     g_col_cnt[NN];
__device__ int     g_pos[NN * NN];                 // [m][n] -> p (col position)

__device__ __forceinline__ unsigned cvt_tf32(float f) {
    unsigned r; asm("cvt.rna.tf32.f32 %0, %1;" : "=r"(r) : "f"(f)); return r;
}
__device__ __forceinline__ void mma_tf32(float c[4], unsigned a0, unsigned a1,
                                         unsigned a2, unsigned a3,
                                         unsigned b0, unsigned b1) {
    asm("mma.sync.aligned.m16n8k8.row.col.f32.tf32.tf32.f32 "
        "{%0,%1,%2,%3},{%4,%5,%6,%7},{%8,%9},{%0,%1,%2,%3};"
        : "+f"(c[0]), "+f"(c[1]), "+f"(c[2]), "+f"(c[3])
        : "r"(a0), "r"(a1), "r"(a2), "r"(a3), "r"(b0), "r"(b1));
}
__device__ __forceinline__ void fma8(float acc[8], float w, uint4 raw) {
    float2 f0 = __half22float2(*(const __half2*)&raw.x);
    float2 f1 = __half22float2(*(const __half2*)&raw.y);
    float2 f2 = __half22float2(*(const __half2*)&raw.z);
    float2 f3 = __half22float2(*(const __half2*)&raw.w);
    acc[0] = fmaf(w, f0.x, acc[0]); acc[1] = fmaf(w, f0.y, acc[1]);
    acc[2] = fmaf(w, f1.x, acc[2]); acc[3] = fmaf(w, f1.y, acc[3]);
    acc[4] = fmaf(w, f2.x, acc[4]); acc[5] = fmaf(w, f2.y, acc[5]);
    acc[6] = fmaf(w, f3.x, acc[6]); acc[7] = fmaf(w, f3.y, acc[7]);
}

// ---------------------------------------------------------------------------
// Kernel 0: row-CSR + col-CSR of (adj>0); col pass also scatters g_pos[m][n].
// ---------------------------------------------------------------------------
__global__ __launch_bounds__(1024) void k_csr(const float* __restrict__ adj) {
    const int tid  = threadIdx.x;
    const int lane = tid & 31;
    const int w    = tid >> 5;               // warp 0..31
    if (blockIdx.y == 0) {
        const int r = blockIdx.x * 32 + w;
        if (r >= NN) return;
        int cnt = 0;
        for (int m0 = 0; m0 < NN; m0 += 32) {
            int m = m0 + lane;
            float v = (m < NN) ? adj[r * NN + m] : 0.f;
            unsigned msk = __ballot_sync(0xffffffffu, v > 0.f);
            if (v > 0.f)
                g_row_idx[r * NN + cnt + __popc(msk & ((1u << lane) - 1u))] = m;
            cnt += __popc(msk);
        }
        if (lane == 0) g_row_cnt[r] = cnt;
    } else {
        __shared__ float tile[32][33];
        const int cbase = blockIdx.x * 32;
        const int c = cbase + w;              // this warp's column
        int cnt = 0;
        for (int n0 = 0; n0 < NN; n0 += 32) {
            int n = n0 + w, m = cbase + lane;
            tile[w][lane] = (n < NN && m < NN) ? adj[n * NN + m] : 0.f;
            __syncthreads();
            if (c < NN) {
                float v = tile[lane][w];
                unsigned msk = __ballot_sync(0xffffffffu, v > 0.f);
                if (v > 0.f) {
                    int p = cnt + __popc(msk & ((1u << lane) - 1u));
                    g_col_idx[c * NN + p] = n0 + lane;
                    g_pos[c * NN + n0 + lane] = p;
                }
                cnt += __popc(msk);
            }
            __syncthreads();
        }
        if (c < NN && lane == 0) g_col_cnt[c] = cnt;
    }
}

// ---------------------------------------------------------------------------
// Kernel 1: Wh = concat(ht,h)@W via tf32 mma (stored fp16); exact fp32 logits
// stored batch-minor as {val, exp(val)} pairs. Batch-half via b0 offset.
// ---------------------------------------------------------------------------
__global__ __launch_bounds__(128) void k_wh(const float* __restrict__ h,
                                            const float* __restrict__ ht,
                                            const float* __restrict__ W,
                                            const float* __restrict__ a,
                                            int b0) {
    const int b     = b0 + blockIdx.y;
    const int rbase = blockIdx.x * 64;
    const int tid   = threadIdx.x;

    __shared__ float xs[64 * XST];
    __shared__ float Ws[64 * XST];
    __shared__ float Wa[128];

    for (int k = tid; k < 1024; k += 128) {
        int i = k >> 4, c4 = (k & 15) * 4;
        *(float4*)&Ws[i * XST + c4] = *(const float4*)&W[i * 64 + c4];
    }
    for (int k = tid; k < 1024; k += 128) {
        int r = k >> 4, c4 = (k & 15) * 4;
        int gr = rbase + r;
        float4 v = make_float4(0.f, 0.f, 0.f, 0.f);
        if (gr < NN) {
            const float* src = (gr < NROW) ? &ht[((size_t)b * NROW + gr) * D]
                                           : &h [((size_t)b * NROW + gr - NROW) * D];
            v = *(const float4*)(src + c4);
        }
        *(float4*)&xs[r * XST + c4] = v;
    }
    __syncthreads();

    {   // Wa[0:64] = W@a[:64], Wa[64:128] = W@a[64:]
        int kk = tid & 63, which = tid >> 6;
        float s = 0.f;
        for (int c = 0; c < 64; c++)
            s = fmaf(Ws[kk * XST + c], a[which * 64 + c], s);
        Wa[which * 64 + kk] = s;
    }
    __syncthreads();

    const int warp = tid >> 5, lane = tid & 31;
    const int g = lane >> 2, t4 = lane & 3;
    const int m0 = warp * 16;
    float acc[8][4];
#pragma unroll
    for (int nt = 0; nt < 8; nt++)
#pragma unroll
        for (int j = 0; j < 4; j++) acc[nt][j] = 0.f;

#pragma unroll
    for (int ks = 0; ks < 64; ks += 8) {
        unsigned A0 = cvt_tf32(xs[(m0 + g)     * XST + ks + t4]);
        unsigned A1 = cvt_tf32(xs[(m0 + g + 8) * XST + ks + t4]);
        unsigned A2 = cvt_tf32(xs[(m0 + g)     * XST + ks + t4 + 4]);
        unsigned A3 = cvt_tf32(xs[(m0 + g + 8) * XST + ks + t4 + 4]);
#pragma unroll
        for (int nt = 0; nt < 8; nt++) {
            unsigned B0 = cvt_tf32(Ws[(ks + t4)     * XST + nt * 8 + g]);
            unsigned B1 = cvt_tf32(Ws[(ks + t4 + 4) * XST + nt * 8 + g]);
            mma_tf32(acc[nt], A0, A1, A2, A3, B0, B1);
        }
    }

#pragma unroll
    for (int nt = 0; nt < 8; nt++) {
        int col = nt * 8 + t4 * 2;
        int r0 = rbase + m0 + g, r1 = r0 + 8;
        __half2 h0 = __floats2half2_rn(acc[nt][0], acc[nt][1]);
        __half2 h1 = __floats2half2_rn(acc[nt][2], acc[nt][3]);
        if (r0 < NN) *(__half2*)&g_Whh[((size_t)b * NN + r0) * D + col] = h0;
        if (r1 < NN) *(__half2*)&g_Whh[((size_t)b * NN + r1) * D + col] = h1;
    }

    {   // Exact fp32 logits + their exps (separable softmax numerators)
        int r = tid & 63, which = tid >> 6;
        float s = 0.f;
#pragma unroll 4
        for (int k2 = 0; k2 < 64; k2++)
            s = fmaf(xs[r * XST + k2], Wa[which * 64 + k2], s);
        int gr = rbase + r;
        if (gr < NN) {
            float2 v = make_float2(s, __expf(s));
            if (which == 0) g_l1[gr * BATCH + b] = v;
            else            g_l2[gr * BATCH + b] = v;
        }
    }
}

// ---------------------------------------------------------------------------
// Kernel 2: normalized attention table. One column per block, 256 threads =
// 32 batches x 8 p-lanes. Width-8 shfl reduces Z; each lane rescales its
// own writes (same-thread RAW via L1, no barrier).
// ---------------------------------------------------------------------------
__global__ __launch_bounds__(256) void k_att(int b0) {
    const int m   = blockIdx.x;
    const int tid = threadIdx.x;
    const int b   = b0 + (tid >> 3);         // 32 batches
    const int pg  = tid & 7;                 // 8 p-lanes
    const int cnt = g_col_cnt[m];
    const float2 l2 = g_l2[m * BATCH + b];
    const int* __restrict__ ci = &g_col_idx[m * NN];
    float* dst = &g_att[(size_t)m * MAXD * BATCH + b];

    float Z = 0.f;
    for (int p = pg; p < cnt; p += 8) {
        float2 a0 = g_l1[__ldg(&ci[p]) * BATCH + b];
        float s = a0.x + l2.x;
        float e = (s > 0.f) ? a0.y * l2.y : __expf(0.2f * s);
        dst[p * BATCH] = e;
        Z += e;
    }
#pragma unroll
    for (int off = 4; off > 0; off >>= 1)
        Z += __shfl_xor_sync(0xffffffffu, Z, off, 8);
    const float zi = 1.f / Z;
    for (int p = pg; p < cnt; p += 8)
        dst[p * BATCH] *= zi;
}

// ---------------------------------------------------------------------------
// Kernel 3: h_prime[b,n,:] = sum_j att * Wh[b,m_j,:]; concat + ELU.
// Block = (n, batch-half): 256 threads = 32 batches x 8 lanes.
// Depth-2 software pipeline.
// ---------------------------------------------------------------------------
__global__ __launch_bounds__(256) void k_out(float* __restrict__ out, int b0) {
    const int n    = blockIdx.x;
    const int tid  = threadIdx.x;
    const int b    = b0 + (tid >> 3);   // 32 batches
    const int lane = tid & 7;
    const int cnt  = g_row_cnt[n];

    __shared__ int2 sjd[MAXD];        // {wh byte-off, att index base}
    if (tid < cnt) {
        int m = g_row_idx[n * NN + tid];
        int p = g_pos[m * NN + n];
        sjd[tid] = make_int2(m << 7, (m * MAXD + p) * BATCH);
    }
    __syncthreads();

    const char* whb = (const char*)g_Whh + (size_t)b * NN * 128 + lane * 16;

    float acc[8];
#pragma unroll
    for (int k = 0; k < 8; k++) acc[k] = 0.f;

    float w0, w1; uint4 r0, r1;
    const int nb = cnt >> 1;          // pairs

    if (nb > 0) {
        int2 d0 = sjd[0], d1 = sjd[1];
        w0 = g_att[d0.y + b]; r0 = *(const uint4*)(whb + d0.x);
        w1 = g_att[d1.y + b]; r1 = *(const uint4*)(whb + d1.x);
        for (int kb = 1; kb < nb; kb++) {
            int2 e0 = sjd[kb * 2], e1 = sjd[kb * 2 + 1];
            float nw0 = g_att[e0.y + b]; uint4 nr0 = *(const uint4*)(whb + e0.x);
            float nw1 = g_att[e1.y + b]; uint4 nr1 = *(const uint4*)(whb + e1.x);
            fma8(acc, w0, r0); fma8(acc, w1, r1);
            w0 = nw0; r0 = nr0; w1 = nw1; r1 = nr1;
        }
        fma8(acc, w0, r0); fma8(acc, w1, r1);
    }
    if (cnt & 1) {
        int2 d = sjd[cnt - 1];
        float wj = g_att[d.y + b];
        uint4 rj = *(const uint4*)(whb + d.x);
        fma8(acc, wj, rj);
    }

#pragma unroll
    for (int k = 0; k < 8; k++)
        acc[k] = (acc[k] > 0.f) ? acc[k] : (__expf(acc[k]) - 1.f);

    size_t ob = (n < NROW) ? (((size_t)b * NROW + n) * 128 + lane * 8)
                           : (((size_t)b * NROW + (n - NROW)) * 128 + 64 + lane * 8);
    *(float4*)(out + ob)     = make_float4(acc[0], acc[1], acc[2], acc[3]);
    *(float4*)(out + ob + 4) = make_float4(acc[4], acc[5], acc[6], acc[7]);
}

// ---------------------------------------------------------------------------
// Launcher: two batch-half chains on separate streams + k_csr on a third;
// capture-safe fork/join (host-only resources, created once).
// ---------------------------------------------------------------------------
extern "C" void kernel_launch(void* const* d_in, const int* in_sizes, int n_in,
                              void* d_out, int out_size) {
    const float* h   = (const float*)d_in[0];
    const float* ht  = (const float*)d_in[1];
    const float* W   = (const float*)d_in[2];
    const float* a   = (const float*)d_in[3];
    const float* adj = (const float*)d_in[4];
    float* out = (float*)d_out;

    static cudaStream_t s_csr = nullptr, s2 = nullptr;
    static cudaEvent_t  eF = nullptr, eC = nullptr, eJ = nullptr;
    if (s_csr == nullptr) {
        cudaStreamCreateWithFlags(&s_csr, cudaStreamNonBlocking);
        cudaStreamCreateWithFlags(&s2,    cudaStreamNonBlocking);
        cudaEventCreateWithFlags(&eF, cudaEventDisableTiming);
        cudaEventCreateWithFlags(&eC, cudaEventDisableTiming);
        cudaEventCreateWithFlags(&eJ, cudaEventDisableTiming);
    }

    // fork
    cudaEventRecord(eF, 0);
    cudaStreamWaitEvent(s_csr, eF, 0);
    cudaStreamWaitEvent(s2,    eF, 0);

    k_csr<<<dim3((NN + 31) / 32, 2), 1024, 0, s_csr>>>(adj);
    cudaEventRecord(eC, s_csr);

    k_wh<<<dim3((NN + 63) / 64, HALF), 128, 0, 0 >>>(h, ht, W, a, 0);
    k_wh<<<dim3((NN + 63) / 64, HALF), 128, 0, s2>>>(h, ht, W, a, HALF);

    cudaStreamWaitEvent(0,  eC, 0);
    cudaStreamWaitEvent(s2, eC, 0);

    k_att<<<NN, 256, 0, 0 >>>(0);
    k_att<<<NN, 256, 0, s2>>>(HALF);

    k_out<<<NN, 256, 0, 0 >>>(out, 0);
    k_out<<<NN, 256, 0, s2>>>(out, HALF);

    // join
    cudaEventRecord(eJ, s2);
    cudaStreamWaitEvent(0, eJ, 0);
}

// round 15
// speedup vs baseline: 1.9952x; 1.1214x over previous
#include <cuda_runtime.h>
#include <cuda_fp16.h>
#include <math.h>

#define BATCH 64
#define HALF  32
#define NROW  307
#define NN    614
#define D     64
#define XST   68   // smem tile stride (conflict-free for mma frag loads)
#define MAXD  128  // hard degree bound
#define UNR   8    // k_att register-resident p-iterations (covers cnt <= 64)

// Scratch (device globals — allocation-free per harness rules)
__device__ __align__(16) __half g_Whh[(size_t)BATCH * NN * D];   // [b][m][c] fp16
__device__ float2  g_l1[NN * BATCH];               // [n][b] = {Wh1, exp(Wh1)}
__device__ float2  g_l2[NN * BATCH];               // [m][b] = {Wh2, exp(Wh2)}
__device__ float   g_att[(size_t)NN * MAXD * BATCH]; // [m][p][b] normalized att
__device__ int     g_row_idx[NN * NN];
__device__ int     g_row_cnt[NN];
__device__ int     g_col_idx[NN * NN];
__device__ int     g_col_cnt[NN];
__device__ int     g_pos[NN * NN];                 // [m][n] -> p (col position)

__device__ __forceinline__ unsigned cvt_tf32(float f) {
    unsigned r; asm("cvt.rna.tf32.f32 %0, %1;" : "=r"(r) : "f"(f)); return r;
}
__device__ __forceinline__ void mma_tf32(float c[4], unsigned a0, unsigned a1,
                                         unsigned a2, unsigned a3,
                                         unsigned b0, unsigned b1) {
    asm("mma.sync.aligned.m16n8k8.row.col.f32.tf32.tf32.f32 "
        "{%0,%1,%2,%3},{%4,%5,%6,%7},{%8,%9},{%0,%1,%2,%3};"
        : "+f"(c[0]), "+f"(c[1]), "+f"(c[2]), "+f"(c[3])
        : "r"(a0), "r"(a1), "r"(a2), "r"(a3), "r"(b0), "r"(b1));
}
__device__ __forceinline__ void fma8(float acc[8], float w, uint4 raw) {
    float2 f0 = __half22float2(*(const __half2*)&raw.x);
    float2 f1 = __half22float2(*(const __half2*)&raw.y);
    float2 f2 = __half22float2(*(const __half2*)&raw.z);
    float2 f3 = __half22float2(*(const __half2*)&raw.w);
    acc[0] = fmaf(w, f0.x, acc[0]); acc[1] = fmaf(w, f0.y, acc[1]);
    acc[2] = fmaf(w, f1.x, acc[2]); acc[3] = fmaf(w, f1.y, acc[3]);
    acc[4] = fmaf(w, f2.x, acc[4]); acc[5] = fmaf(w, f2.y, acc[5]);
    acc[6] = fmaf(w, f3.x, acc[6]); acc[7] = fmaf(w, f3.y, acc[7]);
}

// ---------------------------------------------------------------------------
// Kernel 0: row-CSR + col-CSR of (adj>0); col pass also scatters g_pos[m][n].
// ---------------------------------------------------------------------------
__global__ __launch_bounds__(1024) void k_csr(const float* __restrict__ adj) {
    const int tid  = threadIdx.x;
    const int lane = tid & 31;
    const int w    = tid >> 5;               // warp 0..31
    if (blockIdx.y == 0) {
        const int r = blockIdx.x * 32 + w;
        if (r >= NN) return;
        int cnt = 0;
        for (int m0 = 0; m0 < NN; m0 += 32) {
            int m = m0 + lane;
            float v = (m < NN) ? adj[r * NN + m] : 0.f;
            unsigned msk = __ballot_sync(0xffffffffu, v > 0.f);
            if (v > 0.f)
                g_row_idx[r * NN + cnt + __popc(msk & ((1u << lane) - 1u))] = m;
            cnt += __popc(msk);
        }
        if (lane == 0) g_row_cnt[r] = cnt;
    } else {
        __shared__ float tile[32][33];
        const int cbase = blockIdx.x * 32;
        const int c = cbase + w;              // this warp's column
        int cnt = 0;
        for (int n0 = 0; n0 < NN; n0 += 32) {
            int n = n0 + w, m = cbase + lane;
            tile[w][lane] = (n < NN && m < NN) ? adj[n * NN + m] : 0.f;
            __syncthreads();
            if (c < NN) {
                float v = tile[lane][w];
                unsigned msk = __ballot_sync(0xffffffffu, v > 0.f);
                if (v > 0.f) {
                    int p = cnt + __popc(msk & ((1u << lane) - 1u));
                    g_col_idx[c * NN + p] = n0 + lane;
                    g_pos[c * NN + n0 + lane] = p;
                }
                cnt += __popc(msk);
            }
            __syncthreads();
        }
        if (c < NN && lane == 0) g_col_cnt[c] = cnt;
    }
}

// ---------------------------------------------------------------------------
// Kernel 1: Wh = concat(ht,h)@W via tf32 mma (stored fp16); exact fp32 logits
// stored batch-minor as {val, exp(val)} pairs. Batch-half via b0 offset.
// ---------------------------------------------------------------------------
__global__ __launch_bounds__(128) void k_wh(const float* __restrict__ h,
                                            const float* __restrict__ ht,
                                            const float* __restrict__ W,
                                            const float* __restrict__ a,
                                            int b0) {
    const int b     = b0 + blockIdx.y;
    const int rbase = blockIdx.x * 64;
    const int tid   = threadIdx.x;

    __shared__ float xs[64 * XST];
    __shared__ float Ws[64 * XST];
    __shared__ float Wa[128];

    for (int k = tid; k < 1024; k += 128) {
        int i = k >> 4, c4 = (k & 15) * 4;
        *(float4*)&Ws[i * XST + c4] = *(const float4*)&W[i * 64 + c4];
    }
    for (int k = tid; k < 1024; k += 128) {
        int r = k >> 4, c4 = (k & 15) * 4;
        int gr = rbase + r;
        float4 v = make_float4(0.f, 0.f, 0.f, 0.f);
        if (gr < NN) {
            const float* src = (gr < NROW) ? &ht[((size_t)b * NROW + gr) * D]
                                           : &h [((size_t)b * NROW + gr - NROW) * D];
            v = *(const float4*)(src + c4);
        }
        *(float4*)&xs[r * XST + c4] = v;
    }
    __syncthreads();

    {   // Wa[0:64] = W@a[:64], Wa[64:128] = W@a[64:]
        int kk = tid & 63, which = tid >> 6;
        float s = 0.f;
        for (int c = 0; c < 64; c++)
            s = fmaf(Ws[kk * XST + c], a[which * 64 + c], s);
        Wa[which * 64 + kk] = s;
    }
    __syncthreads();

    const int warp = tid >> 5, lane = tid & 31;
    const int g = lane >> 2, t4 = lane & 3;
    const int m0 = warp * 16;
    float acc[8][4];
#pragma unroll
    for (int nt = 0; nt < 8; nt++)
#pragma unroll
        for (int j = 0; j < 4; j++) acc[nt][j] = 0.f;

#pragma unroll
    for (int ks = 0; ks < 64; ks += 8) {
        unsigned A0 = cvt_tf32(xs[(m0 + g)     * XST + ks + t4]);
        unsigned A1 = cvt_tf32(xs[(m0 + g + 8) * XST + ks + t4]);
        unsigned A2 = cvt_tf32(xs[(m0 + g)     * XST + ks + t4 + 4]);
        unsigned A3 = cvt_tf32(xs[(m0 + g + 8) * XST + ks + t4 + 4]);
#pragma unroll
        for (int nt = 0; nt < 8; nt++) {
            unsigned B0 = cvt_tf32(Ws[(ks + t4)     * XST + nt * 8 + g]);
            unsigned B1 = cvt_tf32(Ws[(ks + t4 + 4) * XST + nt * 8 + g]);
            mma_tf32(acc[nt], A0, A1, A2, A3, B0, B1);
        }
    }

#pragma unroll
    for (int nt = 0; nt < 8; nt++) {
        int col = nt * 8 + t4 * 2;
        int r0 = rbase + m0 + g, r1 = r0 + 8;
        __half2 h0 = __floats2half2_rn(acc[nt][0], acc[nt][1]);
        __half2 h1 = __floats2half2_rn(acc[nt][2], acc[nt][3]);
        if (r0 < NN) *(__half2*)&g_Whh[((size_t)b * NN + r0) * D + col] = h0;
        if (r1 < NN) *(__half2*)&g_Whh[((size_t)b * NN + r1) * D + col] = h1;
    }

    {   // Exact fp32 logits + their exps (separable softmax numerators)
        int r = tid & 63, which = tid >> 6;
        float s = 0.f;
#pragma unroll 4
        for (int k2 = 0; k2 < 64; k2++)
            s = fmaf(xs[r * XST + k2], Wa[which * 64 + k2], s);
        int gr = rbase + r;
        if (gr < NN) {
            float2 v = make_float2(s, __expf(s));
            if (which == 0) g_l1[gr * BATCH + b] = v;
            else            g_l2[gr * BATCH + b] = v;
        }
    }
}

// ---------------------------------------------------------------------------
// Kernel 2: normalized attention — single pass, write-coalesced.
// Block = one column m, 256 threads: b = b0 + (tid&31), pg = tid>>5.
// e values live in registers (UNR=8 covers cnt<=64; fallback for larger);
// Z reduced across the 8 warps via padded smem; one coalesced write pass.
// ---------------------------------------------------------------------------
__global__ __launch_bounds__(256) void k_att(int b0) {
    const int m   = blockIdx.x;
    const int tid = threadIdx.x;
    const int bl  = tid & 31;                // batch lane within half
    const int b   = b0 + bl;
    const int pg  = tid >> 5;                // warp = p-lane (0..7)
    const int cnt = g_col_cnt[m];
    const float2 l2 = g_l2[m * BATCH + b];
    const int* __restrict__ ci = &g_col_idx[m * NN];
    float* dst = &g_att[(size_t)m * MAXD * BATCH + b];

    __shared__ float sZ[8][33];              // padded: conflict-free column sum

    float e[UNR];
    float Z = 0.f;
#pragma unroll
    for (int it = 0; it < UNR; it++) {
        const int p = pg + it * 8;
        e[it] = 0.f;
        if (p < cnt) {
            float2 a0 = g_l1[__ldg(&ci[p]) * BATCH + b];
            float s = a0.x + l2.x;
            e[it] = (s > 0.f) ? a0.y * l2.y : __expf(0.2f * s);
            Z += e[it];
        }
    }
    // correctness fallback for cnt > 64 (never hit at 5% density):
    for (int p = UNR * 8 + pg; p < cnt; p += 8) {
        float2 a0 = g_l1[__ldg(&ci[p]) * BATCH + b];
        float s = a0.x + l2.x;
        float ev = (s > 0.f) ? a0.y * l2.y : __expf(0.2f * s);
        dst[p * BATCH] = ev;                 // store unnormalized; rescaled below
        Z += ev;
    }

    sZ[pg][bl] = Z;
    __syncthreads();
    float zt = 0.f;
#pragma unroll
    for (int k = 0; k < 8; k++) zt += sZ[k][bl];
    const float zi = 1.f / zt;

#pragma unroll
    for (int it = 0; it < UNR; it++) {
        const int p = pg + it * 8;
        if (p < cnt) dst[p * BATCH] = e[it] * zi;
    }
    for (int p = UNR * 8 + pg; p < cnt; p += 8)
        dst[p * BATCH] *= zi;
}

// ---------------------------------------------------------------------------
// Kernel 3: h_prime[b,n,:] = sum_j att * Wh[b,m_j,:]; concat + ELU.
// Block = (n, batch-half): 256 threads = 32 batches x 8 lanes.
// Depth-2 software pipeline.
// ---------------------------------------------------------------------------
__global__ __launch_bounds__(256) void k_out(float* __restrict__ out, int b0) {
    const int n    = blockIdx.x;
    const int tid  = threadIdx.x;
    const int b    = b0 + (tid >> 3);   // 32 batches
    const int lane = tid & 7;
    const int cnt  = g_row_cnt[n];

    __shared__ int2 sjd[MAXD];        // {wh byte-off, att index base}
    if (tid < cnt) {
        int m = g_row_idx[n * NN + tid];
        int p = g_pos[m * NN + n];
        sjd[tid] = make_int2(m << 7, (m * MAXD + p) * BATCH);
    }
    __syncthreads();

    const char* whb = (const char*)g_Whh + (size_t)b * NN * 128 + lane * 16;

    float acc[8];
#pragma unroll
    for (int k = 0; k < 8; k++) acc[k] = 0.f;

    float w0, w1; uint4 r0, r1;
    const int nb = cnt >> 1;          // pairs

    if (nb > 0) {
        int2 d0 = sjd[0], d1 = sjd[1];
        w0 = g_att[d0.y + b]; r0 = *(const uint4*)(whb + d0.x);
        w1 = g_att[d1.y + b]; r1 = *(const uint4*)(whb + d1.x);
        for (int kb = 1; kb < nb; kb++) {
            int2 e0 = sjd[kb * 2], e1 = sjd[kb * 2 + 1];
            float nw0 = g_att[e0.y + b]; uint4 nr0 = *(const uint4*)(whb + e0.x);
            float nw1 = g_att[e1.y + b]; uint4 nr1 = *(const uint4*)(whb + e1.x);
            fma8(acc, w0, r0); fma8(acc, w1, r1);
            w0 = nw0; r0 = nr0; w1 = nw1; r1 = nr1;
        }
        fma8(acc, w0, r0); fma8(acc, w1, r1);
    }
    if (cnt & 1) {
        int2 d = sjd[cnt - 1];
        float wj = g_att[d.y + b];
        uint4 rj = *(const uint4*)(whb + d.x);
        fma8(acc, wj, rj);
    }

#pragma unroll
    for (int k = 0; k < 8; k++)
        acc[k] = (acc[k] > 0.f) ? acc[k] : (__expf(acc[k]) - 1.f);

    size_t ob = (n < NROW) ? (((size_t)b * NROW + n) * 128 + lane * 8)
                           : (((size_t)b * NROW + (n - NROW)) * 128 + 64 + lane * 8);
    *(float4*)(out + ob)     = make_float4(acc[0], acc[1], acc[2], acc[3]);
    *(float4*)(out + ob + 4) = make_float4(acc[4], acc[5], acc[6], acc[7]);
}

// ---------------------------------------------------------------------------
// Launcher: two batch-half chains on separate streams + k_csr on a third;
// capture-safe fork/join (host-only resources, created once).
// ---------------------------------------------------------------------------
extern "C" void kernel_launch(void* const* d_in, const int* in_sizes, int n_in,
                              void* d_out, int out_size) {
    const float* h   = (const float*)d_in[0];
    const float* ht  = (const float*)d_in[1];
    const float* W   = (const float*)d_in[2];
    const float* a   = (const float*)d_in[3];
    const float* adj = (const float*)d_in[4];
    float* out = (float*)d_out;

    static cudaStream_t s_csr = nullptr, s2 = nullptr;
    static cudaEvent_t  eF = nullptr, eC = nullptr, eJ = nullptr;
    if (s_csr == nullptr) {
        cudaStreamCreateWithFlags(&s_csr, cudaStreamNonBlocking);
        cudaStreamCreateWithFlags(&s2,    cudaStreamNonBlocking);
        cudaEventCreateWithFlags(&eF, cudaEventDisableTiming);
        cudaEventCreateWithFlags(&eC, cudaEventDisableTiming);
        cudaEventCreateWithFlags(&eJ, cudaEventDisableTiming);
    }

    // fork
    cudaEventRecord(eF, 0);
    cudaStreamWaitEvent(s_csr, eF, 0);
    cudaStreamWaitEvent(s2,    eF, 0);

    k_csr<<<dim3((NN + 31) / 32, 2), 1024, 0, s_csr>>>(adj);
    cudaEventRecord(eC, s_csr);

    k_wh<<<dim3((NN + 63) / 64, HALF), 128, 0, 0 >>>(h, ht, W, a, 0);
    k_wh<<<dim3((NN + 63) / 64, HALF), 128, 0, s2>>>(h, ht, W, a, HALF);

    cudaStreamWaitEvent(0,  eC, 0);
    cudaStreamWaitEvent(s2, eC, 0);

    k_att<<<NN, 256, 0, 0 >>>(0);
    k_att<<<NN, 256, 0, s2>>>(HALF);

    k_out<<<NN, 256, 0, 0 >>>(out, 0);
    k_out<<<NN, 256, 0, s2>>>(out, HALF);

    // join
    cudaEventRecord(eJ, s2);
    cudaStreamWaitEvent(0, eJ, 0);
}